// round 3
// baseline (speedup 1.0000x reference)
#include <cuda_runtime.h>

// Problem constants (fixed by the reference)
#define BATCH 16
#define CIN   128
#define COUT  128
#define Hh    224
#define Ww    224
#define W4    (Ww / 4)          // 56 float4 per row
#define PLANE  (Hh * Ww)        // 50176 floats per (b,c) plane
#define PLANE4 (PLANE / 4)      // 12544 float4 per plane

// Full-width row-strip tiles: TR output rows, RR = TR+2 region rows (1-row halo)
#define TR   16
#define RR   (TR + 2)           // 18
#define SSTR (Ww + 4)           // smem row stride in floats (228, mult of 4)
#define NCORE (RR * W4)         // 18*56 = 1008 float4 region slots
#define NOUT  (TR * W4)         // 16*56 = 896 float4 output slots
#define NT   256
#define NTILES (Hh / TR)        // 14 strips per image

__global__ __launch_bounds__(NT) void fused_cross_conv(const float* __restrict__ x,
                                                       const float* __restrict__ bias,
                                                       float* __restrict__ out) {
    __shared__ float Csh[RR * SSTR];   // channel-sum region (float4-aligned rows)
    __shared__ float sb[COUT];

    const int tid = threadIdx.x;
    if (tid < COUT) sb[tid] = bias[tid];

    const int bx = blockIdx.x;
    const int b  = bx / NTILES;
    const int t  = bx - b * NTILES;
    const int r0 = t * TR;

    // ---------------- Phase 1: channel sum into smem (all float4, coalesced) ----
    int  coff[4];      // plane-relative float4 offset
    bool cval[4];      // region row inside image?
    int  ci[4], cj[4]; // smem region row / col4
    float4 acc[4];
#pragma unroll
    for (int k = 0; k < 4; k++) {
        int s = tid + k * NT;
        acc[k] = make_float4(0.f, 0.f, 0.f, 0.f);
        if (s < NCORE) {
            int i  = s / W4;
            int j4 = s - i * W4;
            int gr = r0 - 1 + i;
            cval[k] = (gr >= 0) && (gr < Hh);
            coff[k] = gr * W4 + j4;
            ci[k] = i; cj[k] = j4;
        } else {
            cval[k] = false; coff[k] = 0; ci[k] = -1; cj[k] = 0;
        }
    }

    const float4* x4b = reinterpret_cast<const float4*>(x) + (size_t)b * CIN * PLANE4;

#pragma unroll 4
    for (int c = 0; c < CIN; c++) {
        const float4* base = x4b + (size_t)c * PLANE4;
#pragma unroll
        for (int k = 0; k < 4; k++) {
            if (cval[k]) {
                float4 v = __ldcs(base + coff[k]);
                acc[k].x += v.x; acc[k].y += v.y; acc[k].z += v.z; acc[k].w += v.w;
            }
        }
    }

#pragma unroll
    for (int k = 0; k < 4; k++) {
        if (ci[k] >= 0) {
            float4 a = cval[k] ? acc[k] : make_float4(0.f, 0.f, 0.f, 0.f);
            reinterpret_cast<float4*>(Csh + ci[k] * SSTR)[cj[k]] = a;
        }
    }
    __syncthreads();

    // ---------------- Phase 2: 5-pt cross stencil + broadcast to 128 channels ---
    float4* out4b = reinterpret_cast<float4*>(out) + (size_t)b * COUT * PLANE4;

#pragma unroll
    for (int k = 0; k < 4; k++) {
        int s = tid + k * NT;
        if (s < NOUT) {
            int ii = s / W4;
            int j4 = s - ii * W4;
            int i  = ii + 1;                  // region (smem) row
            int cb = 4 * j4;                  // smem col of first output elem

            const float* rowC = Csh + i * SSTR;
            const float* rowU = rowC - SSTR;
            const float* rowD = rowC + SSTR;

            float lm = (cb > 0)        ? rowC[cb - 1] : 0.f;   // image-left pad = 0
            float rp = (cb + 4 < Ww)   ? rowC[cb + 4] : 0.f;   // image-right pad = 0
            float v0 = rowC[cb + 0], v1 = rowC[cb + 1];
            float v2 = rowC[cb + 2], v3 = rowC[cb + 3];

            float4 r;
            r.x = rowU[cb + 0] + rowD[cb + 0] + lm + v1 + v0;
            r.y = rowU[cb + 1] + rowD[cb + 1] + v0 + v2 + v1;
            r.z = rowU[cb + 2] + rowD[cb + 2] + v1 + v3 + v2;
            r.w = rowU[cb + 3] + rowD[cb + 3] + v2 + rp + v3;

            int gr = r0 + ii;
            float4* op = out4b + gr * W4 + j4;
#pragma unroll 4
            for (int o = 0; o < COUT; o++) {
                float bo = sb[o];
                float4 v = make_float4(r.x + bo, r.y + bo, r.z + bo, r.w + bo);
                __stcs(op + (size_t)o * PLANE4, v);
            }
        }
    }
}

extern "C" void kernel_launch(void* const* d_in, const int* in_sizes, int n_in,
                              void* d_out, int out_size) {
    const float* x    = (const float*)d_in[0];   // [16,128,224,224] f32
    const float* bias = (const float*)d_in[2];   // [128] f32
    float* out = (float*)d_out;                  // [16,128,224,224] f32

    fused_cross_conv<<<BATCH * NTILES, NT>>>(x, bias, out);
}

// round 4
// speedup vs baseline: 1.1597x; 1.1597x over previous
#include <cuda_runtime.h>

// Problem constants (fixed by the reference)
#define BATCH 16
#define CIN   128
#define COUT  128
#define Hh    224
#define Ww    224
#define W4    (Ww / 4)          // 56 float4 per row
#define PLANE  (Hh * Ww)        // 50176 floats per (b,c) plane
#define PLANE4 (PLANE / 4)      // 12544 float4 per plane

// Thin full-width row strips: TR output rows, RR = TR+2 region rows (1-row halo)
#define TR   4
#define RR   (TR + 2)           // 6
#define SSTR (Ww + 4)           // smem row stride in floats (228)
#define NCORE (RR * W4)         // 6*56 = 336 float4 region slots
#define NOUT  (TR * W4)         // 4*56 = 224 float4 output slots
#define NT   128
#define NTILES (Hh / TR)        // 56 strips per image

__global__ __launch_bounds__(NT) void fused_cross_conv(const float* __restrict__ x,
                                                       const float* __restrict__ bias,
                                                       float* __restrict__ out) {
    __shared__ float Csh[RR * SSTR];   // channel-sum region
    __shared__ float sb[COUT];

    const int tid = threadIdx.x;
    sb[tid] = bias[tid];               // NT == COUT == 128

    const int bx = blockIdx.x;
    const int b  = bx / NTILES;
    const int t  = bx - b * NTILES;
    const int r0 = t * TR;

    // ---------------- Phase 1: channel sum into smem (all float4, coalesced) ----
    int  coff[3];
    bool cval[3];
    int  csm[3];
    float4 acc[3];
#pragma unroll
    for (int k = 0; k < 3; k++) {
        int s = tid + k * NT;
        acc[k] = make_float4(0.f, 0.f, 0.f, 0.f);
        if (s < NCORE) {
            int i  = s / W4;
            int j4 = s - i * W4;
            int gr = r0 - 1 + i;
            cval[k] = (gr >= 0) && (gr < Hh);
            coff[k] = gr * W4 + j4;
            csm[k]  = i * SSTR + 4 * j4;
        } else {
            cval[k] = false; coff[k] = 0; csm[k] = -1;
        }
    }

    const float4* x4b = reinterpret_cast<const float4*>(x) + (size_t)b * CIN * PLANE4;

#pragma unroll 4
    for (int c = 0; c < CIN; c++) {
        const float4* base = x4b + (size_t)c * PLANE4;
#pragma unroll
        for (int k = 0; k < 3; k++) {
            if (cval[k]) {
                float4 v = __ldcs(base + coff[k]);
                acc[k].x += v.x; acc[k].y += v.y; acc[k].z += v.z; acc[k].w += v.w;
            }
        }
    }

#pragma unroll
    for (int k = 0; k < 3; k++) {
        if (csm[k] >= 0) {
            float4 a = cval[k] ? acc[k] : make_float4(0.f, 0.f, 0.f, 0.f);
            *reinterpret_cast<float4*>(Csh + csm[k]) = a;
        }
    }
    __syncthreads();

    // ---------------- Phase 2: 5-pt cross stencil + broadcast to 128 channels ---
    float4* out4b = reinterpret_cast<float4*>(out) + (size_t)b * COUT * PLANE4;

#pragma unroll
    for (int k = 0; k < 2; k++) {
        int s = tid + k * NT;
        if (s < NOUT) {
            int ii = s / W4;
            int j4 = s - ii * W4;
            int i  = ii + 1;                  // region (smem) row
            int cb = 4 * j4;                  // smem col of first output elem

            const float* rowC = Csh + i * SSTR;
            const float* rowU = rowC - SSTR;
            const float* rowD = rowC + SSTR;

            float lm = (cb > 0)      ? rowC[cb - 1] : 0.f;   // image-left pad
            float rp = (cb + 4 < Ww) ? rowC[cb + 4] : 0.f;   // image-right pad
            float v0 = rowC[cb + 0], v1 = rowC[cb + 1];
            float v2 = rowC[cb + 2], v3 = rowC[cb + 3];

            float4 r;
            r.x = rowU[cb + 0] + rowD[cb + 0] + lm + v1 + v0;
            r.y = rowU[cb + 1] + rowD[cb + 1] + v0 + v2 + v1;
            r.z = rowU[cb + 2] + rowD[cb + 2] + v1 + v3 + v2;
            r.w = rowU[cb + 3] + rowD[cb + 3] + v2 + rp + v3;

            int gr = r0 + ii;
            float4* op = out4b + gr * W4 + j4;
#pragma unroll 4
            for (int o = 0; o < COUT; o++) {
                float bo = sb[o];
                float4 v = make_float4(r.x + bo, r.y + bo, r.z + bo, r.w + bo);
                __stcs(op + (size_t)o * PLANE4, v);
            }
        }
    }
}

extern "C" void kernel_launch(void* const* d_in, const int* in_sizes, int n_in,
                              void* d_out, int out_size) {
    const float* x    = (const float*)d_in[0];   // [16,128,224,224] f32
    const float* bias = (const float*)d_in[2];   // [128] f32
    float* out = (float*)d_out;                  // [16,128,224,224] f32

    fused_cross_conv<<<BATCH * NTILES, NT>>>(x, bias, out);
}

// round 7
// speedup vs baseline: 1.2029x; 1.0372x over previous
#include <cuda_runtime.h>

// Problem constants (fixed by the reference)
#define BATCH 16
#define CIN   128
#define COUT  128
#define Hh    224
#define Ww    224
#define W4    (Ww / 4)          // 56 float4 per row
#define PLANE  (Hh * Ww)        // 50176 floats per (b,c) plane
#define PLANE4 (PLANE / 4)      // 12544 float4 per plane

// Very thin full-width row strips: TR output rows, RR = TR+2 region rows
#define TR   2
#define RR   (TR + 2)           // 4
#define SSTR (Ww + 4)           // smem row stride in floats (228)
#define NCORE (RR * W4)         // 4*56 = 224 float4 region slots
#define NOUT  (TR * W4)         // 2*56 = 112 float4 output slots
#define NT   128
#define NTILES (Hh / TR)        // 112 strips per image

__global__ __launch_bounds__(NT) void fused_cross_conv(const float* __restrict__ x,
                                                       const float* __restrict__ bias,
                                                       float* __restrict__ out) {
    __shared__ float Csh[RR * SSTR];   // channel-sum region
    __shared__ float sb[COUT];

    const int tid = threadIdx.x;
    sb[tid] = bias[tid];               // NT == COUT == 128

    const int bx = blockIdx.x;
    const int b  = bx / NTILES;
    const int t  = bx - b * NTILES;
    const int r0 = t * TR;

    // ---------------- Phase 1: channel sum into smem (all float4, coalesced) ----
    int  coff[2];
    bool cval[2];
    int  csm[2];
    float4 acc[2];
#pragma unroll
    for (int k = 0; k < 2; k++) {
        int s = tid + k * NT;
        acc[k] = make_float4(0.f, 0.f, 0.f, 0.f);
        if (s < NCORE) {
            int i  = s / W4;
            int j4 = s - i * W4;
            int gr = r0 - 1 + i;
            cval[k] = (gr >= 0) && (gr < Hh);
            coff[k] = gr * W4 + j4;
            csm[k]  = i * SSTR + 4 * j4;
        } else {
            cval[k] = false; coff[k] = 0; csm[k] = -1;
        }
    }

    const float4* x4b = reinterpret_cast<const float4*>(x) + (size_t)b * CIN * PLANE4;

#pragma unroll 8
    for (int c = 0; c < CIN; c++) {
        const float4* base = x4b + (size_t)c * PLANE4;
#pragma unroll
        for (int k = 0; k < 2; k++) {
            if (cval[k]) {
                float4 v = __ldcs(base + coff[k]);
                acc[k].x += v.x; acc[k].y += v.y; acc[k].z += v.z; acc[k].w += v.w;
            }
        }
    }

#pragma unroll
    for (int k = 0; k < 2; k++) {
        if (csm[k] >= 0) {
            float4 a = cval[k] ? acc[k] : make_float4(0.f, 0.f, 0.f, 0.f);
            *reinterpret_cast<float4*>(Csh + csm[k]) = a;
        }
    }
    __syncthreads();

    // ---------------- Phase 2: 5-pt cross stencil + broadcast to 128 channels ---
    float4* out4b = reinterpret_cast<float4*>(out) + (size_t)b * COUT * PLANE4;

    if (tid < NOUT) {
        int ii = tid / W4;
        int j4 = tid - ii * W4;
        int i  = ii + 1;                  // region (smem) row
        int cb = 4 * j4;                  // smem col of first output elem

        const float* rowC = Csh + i * SSTR;
        const float* rowU = rowC - SSTR;
        const float* rowD = rowC + SSTR;

        float lm = (cb > 0)      ? rowC[cb - 1] : 0.f;   // image-left pad
        float rp = (cb + 4 < Ww) ? rowC[cb + 4] : 0.f;   // image-right pad
        float v0 = rowC[cb + 0], v1 = rowC[cb + 1];
        float v2 = rowC[cb + 2], v3 = rowC[cb + 3];

        float4 r;
        r.x = rowU[cb + 0] + rowD[cb + 0] + lm + v1 + v0;
        r.y = rowU[cb + 1] + rowD[cb + 1] + v0 + v2 + v1;
        r.z = rowU[cb + 2] + rowD[cb + 2] + v1 + v3 + v2;
        r.w = rowU[cb + 3] + rowD[cb + 3] + v2 + rp + v3;

        int gr = r0 + ii;
        float4* op = out4b + gr * W4 + j4;
#pragma unroll 8
        for (int o = 0; o < COUT; o++) {
            float bo = sb[o];
            float4 v = make_float4(r.x + bo, r.y + bo, r.z + bo, r.w + bo);
            __stcs(op + (size_t)o * PLANE4, v);
        }
    }
}

extern "C" void kernel_launch(void* const* d_in, const int* in_sizes, int n_in,
                              void* d_out, int out_size) {
    const float* x    = (const float*)d_in[0];   // [16,128,224,224] f32
    const float* bias = (const float*)d_in[2];   // [128] f32
    float* out = (float*)d_out;                  // [16,128,224,224] f32

    fused_cross_conv<<<BATCH * NTILES, NT>>>(x, bias, out);
}